// round 16
// baseline (speedup 1.0000x reference)
#include <cuda_runtime.h>
#include <cstdint>
#include <math.h>

#define Bn 32
#define Qn 300
#define Cn 81
#define Pn 300
#define An 29

#define LEN_SCORES ((size_t)Bn * Qn)                        // 9600
#define LEN_LABELS ((size_t)Bn * Qn)                        // 9600
#define LEN_BOXES  ((size_t)Bn * Qn * 4)                    // 38400
#define LEN_SCORE  ((size_t)Bn * An * Qn * (Qn + 1))        // 83,798,400
#define LEN_HMASK  ((size_t)Bn * Qn)                        // 9600
#define LEN_OMASK  ((size_t)Bn * (Qn + 1))                  // 9632

#define OFF_SCORES ((size_t)0)
#define OFF_LABELS (OFF_SCORES + LEN_SCORES)
#define OFF_BOXES  (OFF_LABELS + LEN_LABELS)
#define OFF_SCORE  (OFF_BOXES  + LEN_BOXES)
#define OFF_HMASK  (OFF_SCORE  + LEN_SCORE)
#define OFF_OMASK  (OFF_HMASK  + LEN_HMASK)

#define PLANE_ELEMS (Qn * (Qn + 1))        // 90300
#define PLANE_BLOCKS (Bn * An)             // 928
#define ROW_BLOCKS_10 960                  // 960 * 10 warps = 9600 rows exact
#define GRID_TOTAL (PLANE_BLOCKS + ROW_BLOCKS_10)   // 1888
#define INTERLEAVED (2 * PLANE_BLOCKS)     // 1856: evens=planes, odds=rows

// Last-wins claim scratch. Zero-init at module load. Every plane-block of a
// batch issues the identical, complete atomicMax set for its batch, so after
// a block's own atomics + __syncthreads, its reads see the final values
// (monotonic max, idempotent across blocks and across calls).
__device__ int g_claim[(size_t)Bn * PLANE_ELEMS];

// ---------------------------------------------------------------------------
// Single post-memset kernel (linear graph: memset -> this), 1888 blocks x 320.
// Block mapping INTERLEAVES plane and row blocks so every scheduling wave
// carries a ~50/50 mix: plane latency chains hide under row ALU work on the
// same SMs (and both overlap the memset's L2-drain).
//   blk < 1856:  even -> plane (blk/2),  odd -> row-block (blk/2)
//   blk >= 1856: row-block (928 + blk - 1856)
// Plane block (b,a): own-batch claim atomics + sigmoid, sync, winner stores.
// Row block: 10 warps, one (b,q) row per warp (softmax/boxes/masks).
// ---------------------------------------------------------------------------
__global__ void __launch_bounds__(320) post_kernel(
        const float* __restrict__ logits,
        const float* __restrict__ boxes_in,
        const float* __restrict__ actions,
        const void*  __restrict__ pairs_raw,
        const float* __restrict__ tsizes,
        float* __restrict__ out) {

    int blk = blockIdx.x;
    int tid = threadIdx.x;

    bool is_plane = (blk < INTERLEAVED) && ((blk & 1) == 0);

    if (is_plane) {
        // ---------------- plane block (b, a) ----------------
        int pblk = blk >> 1;               // 0..927
        int b = pblk / An;
        int a = pblk - b * An;

        __shared__ int is64_s;

        // dtype detection (int32 vs int64 pairs): int64 values in [0,Q)
        // have all-zero odd 32-bit words.
        if (tid < 32) {
            const int* pw = (const int*)pairs_raw;
            int nonzero = (pw[2 * tid + 1] != 0) ? 1 : 0;
            unsigned m = __ballot_sync(0xffffffffu, nonzero);
            if (tid == 0) is64_s = (m == 0u) ? 1 : 0;
        }
        __syncthreads();
        bool is64 = (is64_s != 0);

        int* claim_b = g_claim + (size_t)b * PLANE_ELEMS;

        int   k = -1;
        float v = 0.f;
        if (tid < Pn) {
            int p = tid;
            int h, o;
            if (is64) {
                const long long* p64 = (const long long*)pairs_raw + (size_t)b * Pn * 2;
                h = (int)p64[2 * p];
                o = (int)p64[2 * p + 1];
            } else {
                const int* p32 = (const int*)pairs_raw + (size_t)b * Pn * 2;
                h = p32[2 * p];
                o = p32[2 * p + 1];
            }
            if (h == o) o = Qn;
            k = h * (Qn + 1) + o;
            atomicMax(&claim_b[k], p + 1);            // own-batch full claim set
            float x = actions[((size_t)b * Pn + p) * An + a];
            v = 1.f / (1.f + __expf(-x));
        }
        __syncthreads();   // own atomics complete & ordered before claim reads

        if (tid < Pn && claim_b[k] == tid + 1) {
            float* plane = out + OFF_SCORE + (size_t)pblk * PLANE_ELEMS;
            plane[k] = v;  // winner store over the memset zeros
        }

    } else {
        // ---------------- rows block: 10 warps, one (b,q) row each -------
        int rblk = (blk < INTERLEAVED) ? (blk >> 1)
                                       : (PLANE_BLOCKS + blk - INTERLEAVED);
        int wid  = tid >> 5;
        int lane = tid & 31;
        int gwarp = rblk * 10 + wid;                   // < 9600 exactly
        int b = gwarp / Qn;
        int q = gwarp - b * Qn;

        const float* row = logits + (size_t)gwarp * Cn;

        float v0 = row[lane];                                     // 0..31
        float v1 = row[lane + 32];                                // 32..63
        float v2 = (lane + 64 < Cn) ? row[lane + 64] : -INFINITY; // 64..80

        // Argmax over first C-1 = 80 classes (first-index-wins on ties)
        float bv = v0; int bi = lane;
        if (v1 > bv) { bv = v1; bi = lane + 32; }
        if (lane + 64 < Cn - 1 && v2 > bv) { bv = v2; bi = lane + 64; }
        #pragma unroll
        for (int off = 16; off > 0; off >>= 1) {
            float ov = __shfl_xor_sync(0xffffffffu, bv, off);
            int   oi = __shfl_xor_sync(0xffffffffu, bi, off);
            if (ov > bv || (ov == bv && oi < bi)) { bv = ov; bi = oi; }
        }

        // Softmax shifted by bv (max of first 80): score = 1/sum.
        float s = __expf(v0 - bv) + __expf(v1 - bv);
        if (lane + 64 < Cn) s += __expf(v2 - bv);
        #pragma unroll
        for (int off = 16; off > 0; off >>= 1)
            s += __shfl_xor_sync(0xffffffffu, s, off);

        float score = 1.f / s;

        if (lane == 0) {
            out[OFF_SCORES + gwarp] = score;
            out[OFF_LABELS + gwarp] = (float)bi;
            out[OFF_HMASK  + gwarp] = (bi == 1 && score > 0.f) ? 1.f : 0.f;
            out[OFF_OMASK + (size_t)b * (Qn + 1) + q] = (score > 0.f) ? 1.f : 0.f;
            if (q == 0)
                out[OFF_OMASK + (size_t)b * (Qn + 1) + Qn] = 1.f;
        }

        // Boxes: cxcywh -> xyxy scaled by [w,h,w,h]
        if (lane < 4) {
            float cxy = boxes_in[(size_t)gwarp * 4 + (lane & 1)];
            float wh  = boxes_in[(size_t)gwarp * 4 + 2 + (lane & 1)];
            float v   = cxy + ((lane < 2) ? -0.5f : 0.5f) * wh;
            float img_h = tsizes[b * 2 + 0];
            float img_w = tsizes[b * 2 + 1];
            float scale = (lane & 1) ? img_h : img_w;
            out[OFF_BOXES + (size_t)gwarp * 4 + lane] = v * scale;
        }
    }
}

extern "C" void kernel_launch(void* const* d_in, const int* in_sizes, int n_in,
                              void* d_out, int out_size) {
    const float* pred_logits    = (const float*)d_in[0];  // (B,Q,C)
    const float* pred_boxes     = (const float*)d_in[1];  // (B,Q,4)
    const float* pred_actions   = (const float*)d_in[2];  // (B,P,A)
    const void*  pred_rel_pairs = d_in[3];                // (B,P,2) int32/int64
    const float* target_sizes   = (const float*)d_in[4];  // (B,2)

    float* out = (float*)d_out;

    // Node 1: driver memset of the score region (~6.4 TB/s, proven fastest)
    cudaMemsetAsync(out + OFF_SCORE, 0, LEN_SCORE * sizeof(float), 0);

    // Node 2: interleaved planes + rows, one wide launch
    post_kernel<<<GRID_TOTAL, 320>>>(pred_logits, pred_boxes, pred_actions,
                                     pred_rel_pairs, target_sizes, out);
}

// round 17
// speedup vs baseline: 1.1835x; 1.1835x over previous
#include <cuda_runtime.h>
#include <cstdint>
#include <math.h>

#define Bn 32
#define Qn 300
#define Cn 81
#define Pn 300
#define An 29

#define LEN_SCORES ((size_t)Bn * Qn)
#define LEN_LABELS ((size_t)Bn * Qn)
#define LEN_BOXES  ((size_t)Bn * Qn * 4)
#define LEN_SCORE  ((size_t)Bn * An * Qn * (Qn + 1))
#define LEN_HMASK  ((size_t)Bn * Qn)
#define LEN_OMASK  ((size_t)Bn * (Qn + 1))

#define OFF_SCORES ((size_t)0)
#define OFF_LABELS (OFF_SCORES + LEN_SCORES)
#define OFF_BOXES  (OFF_LABELS + LEN_LABELS)
#define OFF_SCORE  (OFF_BOXES  + LEN_BOXES)        // byte offset 230400: 16B ok
#define OFF_HMASK  (OFF_SCORE  + LEN_SCORE)
#define OFF_OMASK  (OFF_HMASK  + LEN_HMASK)

#define PLANE_ELEMS (Qn * (Qn + 1))        // 90300 floats = 361200 bytes
#define PLANE_BYTES (PLANE_ELEMS * 4)
#define CHUNK_BYTES 24080                  // 16B-aligned; 15 * 24080 = 361200
#define NCHUNKS     15

#define PLANE_BLOCKS (Bn * An)             // 928
#define ROW_BLOCKS_4 2400                  // 2400 * 4 warps = 9600 rows exact
#define GRID_TOTAL (PLANE_BLOCKS + ROW_BLOCKS_4)

// Last-wins claim scratch. Zero-init at module load. Every plane-block of a
// batch issues the identical, complete atomicMax set for its batch, so after
// a block's own atomics + __syncthreads, its reads see the final values
// (monotonic max, idempotent across blocks and across calls). Proven R9/R11.
__device__ int g_claim[(size_t)Bn * PLANE_ELEMS];

__device__ __forceinline__ uint32_t smem_u32(const void* p) {
    uint32_t a;
    asm("{ .reg .u64 t; cvta.to.shared.u64 t, %1; cvt.u32.u64 %0, t; }"
        : "=r"(a) : "l"(p));
    return a;
}

// ---------------------------------------------------------------------------
// Single kernel, 3328 blocks x 128. No memset node.
// Blocks [0, 928): plane (b,a) —
//   zero a 24KB smem buffer, claim atomics + sigmoid (regs),
//   issue 15 TMA bulk stores of smem zeros covering the whole plane
//   (memset-class LTS path, overlaps ALL SM work machine-wide),
//   wait_group 0, sync, scattered winner stores over the zeros.
// Blocks [928, 3328): rows, 4 warps per block, one (b,q) row per warp.
// ---------------------------------------------------------------------------
__global__ void __launch_bounds__(128) fused_tma_kernel(
        const float* __restrict__ logits,
        const float* __restrict__ boxes_in,
        const float* __restrict__ actions,
        const void*  __restrict__ pairs_raw,
        const float* __restrict__ tsizes,
        float* __restrict__ out) {

    __shared__ __align__(16) char zbuf[CHUNK_BYTES];

    int blk = blockIdx.x;
    int tid = threadIdx.x;

    if (blk < PLANE_BLOCKS) {
        // ---------------- plane block (b, a) ----------------
        int b = blk / An;
        int a = blk - b * An;

        __shared__ int is64_s;

        // Zero the smem source buffer (float4: 1505 vecs / 128 threads)
        {
            float4* z4 = (float4*)zbuf;
            float4 z = make_float4(0.f, 0.f, 0.f, 0.f);
            for (int i = tid; i < CHUNK_BYTES / 16; i += 128)
                z4[i] = z;
        }

        // dtype detection (int32 vs int64 pairs): int64 values in [0,Q)
        // have all-zero odd 32-bit words.
        if (tid < 32) {
            const int* pw = (const int*)pairs_raw;
            int nonzero = (pw[2 * tid + 1] != 0) ? 1 : 0;
            unsigned m = __ballot_sync(0xffffffffu, nonzero);
            if (tid == 0) is64_s = (m == 0u) ? 1 : 0;
        }
        __syncthreads();
        bool is64 = (is64_s != 0);

        int* claim_b = g_claim + (size_t)b * PLANE_ELEMS;

        // Claim preamble: p = tid, tid+128, tid+256 (3 slots, regs)
        int   kk[3];
        float vv[3];
        #pragma unroll
        for (int j = 0; j < 3; ++j) {
            kk[j] = -1;
            int p = tid + j * 128;
            if (p < Pn) {
                int h, o;
                if (is64) {
                    const long long* p64 = (const long long*)pairs_raw + (size_t)b * Pn * 2;
                    h = (int)p64[2 * p];
                    o = (int)p64[2 * p + 1];
                } else {
                    const int* p32 = (const int*)pairs_raw + (size_t)b * Pn * 2;
                    h = p32[2 * p];
                    o = p32[2 * p + 1];
                }
                if (h == o) o = Qn;
                kk[j] = h * (Qn + 1) + o;
                atomicMax(&claim_b[kk[j]], p + 1);
                float x = actions[((size_t)b * Pn + p) * An + a];
                vv[j] = 1.f / (1.f + __expf(-x));
            }
        }

        // Issue the 15 bulk stores (zeros -> plane) from one thread
        if (tid == 0) {
            asm volatile("fence.proxy.async.shared::cta;" ::: "memory");
            uint32_t src = smem_u32(zbuf);
            char* dst = (char*)(out + OFF_SCORE) + (size_t)blk * PLANE_BYTES;
            #pragma unroll
            for (int c = 0; c < NCHUNKS; ++c) {
                asm volatile(
                    "cp.async.bulk.global.shared::cta.bulk_group [%0], [%1], %2;"
                    :: "l"(dst + (size_t)c * CHUNK_BYTES), "r"(src),
                       "r"((unsigned)CHUNK_BYTES)
                    : "memory");
            }
            asm volatile("cp.async.bulk.commit_group;" ::: "memory");
            asm volatile("cp.async.bulk.wait_group 0;" ::: "memory");
        }
        __syncthreads();   // zeros landed + own atomics complete

        // Winner stores over the zeros
        float* plane = out + OFF_SCORE + (size_t)blk * PLANE_ELEMS;
        #pragma unroll
        for (int j = 0; j < 3; ++j) {
            int p = tid + j * 128;
            if (p < Pn && claim_b[kk[j]] == p + 1)
                plane[kk[j]] = vv[j];
        }

    } else {
        // ---------------- rows block: 4 warps, one (b,q) row each --------
        int wid  = tid >> 5;
        int lane = tid & 31;
        int gwarp = (blk - PLANE_BLOCKS) * 4 + wid;    // < 9600 exactly
        int b = gwarp / Qn;
        int q = gwarp - b * Qn;

        const float* row = logits + (size_t)gwarp * Cn;

        float v0 = row[lane];                                     // 0..31
        float v1 = row[lane + 32];                                // 32..63
        float v2 = (lane + 64 < Cn) ? row[lane + 64] : -INFINITY; // 64..80

        // Argmax over first C-1 = 80 classes (first-index-wins on ties)
        float bv = v0; int bi = lane;
        if (v1 > bv) { bv = v1; bi = lane + 32; }
        if (lane + 64 < Cn - 1 && v2 > bv) { bv = v2; bi = lane + 64; }
        #pragma unroll
        for (int off = 16; off > 0; off >>= 1) {
            float ov = __shfl_xor_sync(0xffffffffu, bv, off);
            int   oi = __shfl_xor_sync(0xffffffffu, bi, off);
            if (ov > bv || (ov == bv && oi < bi)) { bv = ov; bi = oi; }
        }

        // Softmax shifted by bv (max of first 80): score = 1/sum.
        float s = __expf(v0 - bv) + __expf(v1 - bv);
        if (lane + 64 < Cn) s += __expf(v2 - bv);
        #pragma unroll
        for (int off = 16; off > 0; off >>= 1)
            s += __shfl_xor_sync(0xffffffffu, s, off);

        float score = 1.f / s;

        if (lane == 0) {
            out[OFF_SCORES + gwarp] = score;
            out[OFF_LABELS + gwarp] = (float)bi;
            out[OFF_HMASK  + gwarp] = (bi == 1 && score > 0.f) ? 1.f : 0.f;
            out[OFF_OMASK + (size_t)b * (Qn + 1) + q] = (score > 0.f) ? 1.f : 0.f;
            if (q == 0)
                out[OFF_OMASK + (size_t)b * (Qn + 1) + Qn] = 1.f;
        }

        // Boxes: cxcywh -> xyxy scaled by [w,h,w,h]
        if (lane < 4) {
            float cxy = boxes_in[(size_t)gwarp * 4 + (lane & 1)];
            float wh  = boxes_in[(size_t)gwarp * 4 + 2 + (lane & 1)];
            float v   = cxy + ((lane < 2) ? -0.5f : 0.5f) * wh;
            float img_h = tsizes[b * 2 + 0];
            float img_w = tsizes[b * 2 + 1];
            float scale = (lane & 1) ? img_h : img_w;
            out[OFF_BOXES + (size_t)gwarp * 4 + lane] = v * scale;
        }
    }
}

extern "C" void kernel_launch(void* const* d_in, const int* in_sizes, int n_in,
                              void* d_out, int out_size) {
    const float* pred_logits    = (const float*)d_in[0];  // (B,Q,C)
    const float* pred_boxes     = (const float*)d_in[1];  // (B,Q,4)
    const float* pred_actions   = (const float*)d_in[2];  // (B,P,A)
    const void*  pred_rel_pairs = d_in[3];                // (B,P,2) int32/int64
    const float* target_sizes   = (const float*)d_in[4];  // (B,2)

    float* out = (float*)d_out;

    // ONE launch: TMA bulk-store zeroing (memset-class path) overlapped with
    // claim + sigmoid + rows on the SMs. No memset node, no node gaps.
    fused_tma_kernel<<<GRID_TOTAL, 128>>>(pred_logits, pred_boxes,
                                          pred_actions, pred_rel_pairs,
                                          target_sizes, out);
}